// round 9
// baseline (speedup 1.0000x reference)
#include <cuda_runtime.h>
#include <cuda_bf16.h>
#include <cstdint>

#define D_EMBED 512
#define N_CLUST 64
#define ROWS_CTA 512
#define NWARP 16
#define CHUNKS 16                           // 16 chunks x 32 dims
#define STG_W 4096                          // per-warp stage: 32 rows x 128B
#define STG_BYTES (NWARP * STG_W)           // 64KB per stage
#define B_OFF (2 * STG_BYTES)               // 131072
#define SC2_OFF (B_OFF + 65536)             // 196608
#define SWP_OFF (SC2_OFF + 256)             // 196864
#define SMEM_BYTES (SWP_OFF + NWARP * 4)    // 196928

// ---------------- device scratch (no allocations allowed) ----------------
__device__ float  g_c2[N_CLUST];
__device__ double g_acc;
__device__ __align__(16) uint2 g_bfrag[32 * 8 * 32];  // [kstep][ntile][lane] -> 2x bf16x2

// ---------------- helpers ----------------
__device__ __forceinline__ unsigned pack_bf16(float lo, float hi) {
    unsigned r;
    asm("cvt.rn.bf16x2.f32 %0, %1, %2;" : "=r"(r) : "f"(hi), "f"(lo));
    return r;
}
__device__ __forceinline__ void mma16816(float* c,
                                         unsigned a0, unsigned a1, unsigned a2, unsigned a3,
                                         unsigned b0, unsigned b1) {
    asm volatile(
        "mma.sync.aligned.m16n8k16.row.col.f32.bf16.bf16.f32 "
        "{%0,%1,%2,%3}, {%4,%5,%6,%7}, {%8,%9}, {%0,%1,%2,%3};"
        : "+f"(c[0]), "+f"(c[1]), "+f"(c[2]), "+f"(c[3])
        : "r"(a0), "r"(a1), "r"(a2), "r"(a3), "r"(b0), "r"(b1));
}
__device__ __forceinline__ void cp16(unsigned dst, const float* src) {
    asm volatile("cp.async.cg.shared.global [%0], [%1], 16;" :: "r"(dst), "l"(src));
}
#define CP_COMMIT() asm volatile("cp.async.commit_group;" ::: "memory")
#define CP_WAIT1()  asm volatile("cp.async.wait_group 1;" ::: "memory")

__device__ __forceinline__ float4 lds128(unsigned addr) {
    float4 v;
    asm volatile("ld.shared.v4.f32 {%0,%1,%2,%3}, [%4];"
                 : "=f"(v.x), "=f"(v.y), "=f"(v.z), "=f"(v.w) : "r"(addr));
    return v;
}
__device__ __forceinline__ unsigned smem_u32(const void* p) {
    unsigned a;
    asm("{ .reg .u64 t; cvta.to.shared.u64 t, %1; cvt.u32.u64 %0, t; }" : "=r"(a) : "l"(p));
    return a;
}

// alpha may arrive as int32 / int64 / float32 (python scalar 100). Decode robustly.
__device__ __forceinline__ float decode_alpha(const void* p) {
    int iv = *reinterpret_cast<const int*>(p);
    unsigned u = (unsigned)iv;
    unsigned ex = (u >> 23) & 0xffu;
    if (ex >= 110u && ex <= 150u) return __int_as_float(iv);
    if (iv == 0) {
        double dv = *reinterpret_cast<const double*>(p);
        if (dv > 1e-6 && dv < 1e9) return (float)dv;
    }
    return (float)iv;
}

// ---------------- kernel 1: c2 + zero accumulator ----------------
__global__ void prep_kernel(const float* __restrict__ cent) {
    if (blockIdx.x == 0 && threadIdx.x == 0) g_acc = 0.0;
    int w = blockIdx.x * (blockDim.x >> 5) + (threadIdx.x >> 5);
    int lane = threadIdx.x & 31;
    if (w < N_CLUST) {
        const float* c = cent + w * D_EMBED;
        float s = 0.f;
        #pragma unroll
        for (int i = 0; i < D_EMBED / 32; i++) {
            float v = c[i * 32 + lane];
            s = fmaf(v, v, s);
        }
        #pragma unroll
        for (int m = 16; m; m >>= 1) s += __shfl_xor_sync(0xffffffffu, s, m);
        if (lane == 0) g_c2[w] = s;
    }
}

// ---------------- kernel 2: centroids -> bf16 MMA B-fragment layout ----------------
// k-permutation: logical k-pairs of the m16n8k16 B fragment map to physical
// columns (tig*4+{0,1}) / (tig*4+{2,3}) so the A side consumes contiguous 16B.
__global__ void fill_kernel(const float* __restrict__ cent) {
    int id = blockIdx.x * blockDim.x + threadIdx.x;   // 0..8191
    int lane = id & 31, nt = (id >> 5) & 7, ks = id >> 8;
    int n  = nt * 8 + (lane >> 2);
    int kb = ks * 16 + (lane & 3) * 4;
    float4 v = *reinterpret_cast<const float4*>(cent + n * D_EMBED + kb);
    uint2 r;
    r.x = pack_bf16(v.x, v.y);
    r.y = pack_bf16(v.z, v.w);
    g_bfrag[id] = r;
}

// ---------------- kernel 3: main fused GEMM + softmax ----------------
__global__ __launch_bounds__(512, 1)
void main_kernel(const float* __restrict__ x, const void* __restrict__ alphap) {
    extern __shared__ unsigned char smem_raw[];
    uint2* sB  = reinterpret_cast<uint2*>(smem_raw + B_OFF);
    float* sc2 = reinterpret_cast<float*>(smem_raw + SC2_OFF);
    float* swp = reinterpret_cast<float*>(smem_raw + SWP_OFF);

    int tid = threadIdx.x;
    unsigned sbase = smem_u32(smem_raw);

    {   // resident B-fragment copy (64KB) + c2
        const uint4* src = reinterpret_cast<const uint4*>(g_bfrag);
        uint4* dst = reinterpret_cast<uint4*>(sB);
        #pragma unroll
        for (int i = 0; i < 8; i++) dst[i * 512 + tid] = src[i * 512 + tid];
        if (tid < N_CLUST) sc2[tid] = g_c2[tid];
    }
    __syncthreads();

    int warp = tid >> 5, lane = tid & 31;
    int g = lane >> 2, tig = lane & 3;
    size_t base = (size_t)blockIdx.x * ROWS_CTA + (size_t)warp * 32;

    // staging geometry (coalesced): instr i covers rows i*4 + (lane>>3),
    // 128B per row; lane supplies bytes (lane&7)*16 of that row.
    const float* xw = x + base * D_EMBED;
    int srow = lane >> 3, scol = lane & 7;
    unsigned st_w = sbase + warp * STG_W;   // stage 0 base for this warp

    // MMA-phase LDS rows: {g, g+8, g+16, g+24}; col slot = (ki*4+tig)^g (swizzle)
    unsigned ld_off0 = (unsigned)(g * 128) + ((unsigned)((0 * 4 + tig) ^ g) << 4);
    unsigned ld_off1 = (unsigned)(g * 128) + ((unsigned)((1 * 4 + tig) ^ g) << 4);

    float acc[2][8][4];
    #pragma unroll
    for (int m = 0; m < 2; m++)
        #pragma unroll
        for (int n = 0; n < 8; n++)
            #pragma unroll
            for (int j = 0; j < 4; j++) acc[m][n][j] = 0.f;

    float xs[4] = {0.f, 0.f, 0.f, 0.f};
    const uint2* bl = sB + lane;

    // ---- prologue: stage chunks 0 and 1 ----
    #pragma unroll
    for (int p = 0; p < 2; p++) {
        unsigned sb = st_w + (unsigned)(p * STG_BYTES);
        #pragma unroll
        for (int i = 0; i < 8; i++) {
            int rl = i * 4 + srow;
            unsigned dst = sb + (unsigned)(rl * 128) + ((unsigned)(scol ^ (rl & 7)) << 4);
            cp16(dst, xw + (size_t)rl * D_EMBED + p * 32 + scol * 4);
        }
        CP_COMMIT();
    }

    for (int c = 0; c < CHUNKS; c++) {
        CP_WAIT1();  // chunk c staged (c+1 may still be in flight)
        unsigned sb = st_w + (unsigned)((c & 1) * STG_BYTES);

        // load all x for this chunk (2 ksteps) BEFORE overwriting issue
        float4 v[8];
        #pragma unroll
        for (int ki = 0; ki < 2; ki++) {
            unsigned lo = (ki == 0) ? ld_off0 : ld_off1;
            v[ki * 4 + 0] = lds128(sb + lo);
            v[ki * 4 + 1] = lds128(sb + lo + 8  * 128);
            v[ki * 4 + 2] = lds128(sb + lo + 16 * 128);
            v[ki * 4 + 3] = lds128(sb + lo + 24 * 128);
        }

        // stage chunk c+2 into the buffer just consumed
        if (c < CHUNKS - 2) {
            unsigned sb2 = st_w + (unsigned)((c & 1) * STG_BYTES);
            #pragma unroll
            for (int i = 0; i < 8; i++) {
                int rl = i * 4 + srow;
                unsigned dst = sb2 + (unsigned)(rl * 128) + ((unsigned)(scol ^ (rl & 7)) << 4);
                cp16(dst, xw + (size_t)rl * D_EMBED + (c + 2) * 32 + scol * 4);
            }
        }
        CP_COMMIT();  // empty group in tail keeps wait_group numbering exact

        #pragma unroll
        for (int ki = 0; ki < 2; ki++) {
            float4 c00 = v[ki * 4 + 0], c01 = v[ki * 4 + 1];
            float4 c10 = v[ki * 4 + 2], c11 = v[ki * 4 + 3];

            xs[0] = fmaf(c00.x, c00.x, fmaf(c00.y, c00.y, fmaf(c00.z, c00.z, fmaf(c00.w, c00.w, xs[0]))));
            xs[1] = fmaf(c01.x, c01.x, fmaf(c01.y, c01.y, fmaf(c01.z, c01.z, fmaf(c01.w, c01.w, xs[1]))));
            xs[2] = fmaf(c10.x, c10.x, fmaf(c10.y, c10.y, fmaf(c10.z, c10.z, fmaf(c10.w, c10.w, xs[2]))));
            xs[3] = fmaf(c11.x, c11.x, fmaf(c11.y, c11.y, fmaf(c11.z, c11.z, fmaf(c11.w, c11.w, xs[3]))));

            unsigned a0m0 = pack_bf16(c00.x, c00.y), a2m0 = pack_bf16(c00.z, c00.w);
            unsigned a1m0 = pack_bf16(c01.x, c01.y), a3m0 = pack_bf16(c01.z, c01.w);
            unsigned a0m1 = pack_bf16(c10.x, c10.y), a2m1 = pack_bf16(c10.z, c10.w);
            unsigned a1m1 = pack_bf16(c11.x, c11.y), a3m1 = pack_bf16(c11.z, c11.w);

            const uint2* bk = bl + (c * 2 + ki) * 256;
            #pragma unroll
            for (int nt = 0; nt < 8; nt++) {
                uint2 b = bk[nt * 32];
                mma16816(acc[0][nt], a0m0, a1m0, a2m0, a3m0, b.x, b.y);
                mma16816(acc[1][nt], a0m1, a1m1, a2m1, a3m1, b.x, b.y);
            }
        }
    }

    // complete x^2 across the 4-lane tig group (same rows)
    #pragma unroll
    for (int i = 0; i < 4; i++) {
        xs[i] += __shfl_xor_sync(0xffffffffu, xs[i], 1);
        xs[i] += __shfl_xor_sync(0xffffffffu, xs[i], 2);
    }

    float alpha = decode_alpha(alphap);

    // softmax shift-invariance in x^2: sum(dist*soft) = x2 + sum(t*soft), t = c2 - 2*cross
    float rowsum = 0.f;
    #pragma unroll
    for (int m = 0; m < 2; m++) {
        #pragma unroll
        for (int h = 0; h < 2; h++) {
            float dd[16];
            float tmin = 3.4e38f;
            #pragma unroll
            for (int nt = 0; nt < 8; nt++) {
                int n = nt * 8 + tig * 2;
                float t0 = sc2[n]     - 2.f * acc[m][nt][h * 2 + 0];
                float t1 = sc2[n + 1] - 2.f * acc[m][nt][h * 2 + 1];
                dd[nt * 2]     = t0;
                dd[nt * 2 + 1] = t1;
                tmin = fminf(tmin, fminf(t0, t1));
            }
            tmin = fminf(tmin, __shfl_xor_sync(0xffffffffu, tmin, 1));
            tmin = fminf(tmin, __shfl_xor_sync(0xffffffffu, tmin, 2));
            float se = 0.f, sw = 0.f;
            #pragma unroll
            for (int i = 0; i < 16; i++) {
                float e = __expf(alpha * (tmin - dd[i]));
                se += e;
                sw = fmaf(dd[i], e, sw);
            }
            se += __shfl_xor_sync(0xffffffffu, se, 1);
            se += __shfl_xor_sync(0xffffffffu, se, 2);
            sw += __shfl_xor_sync(0xffffffffu, sw, 1);
            sw += __shfl_xor_sync(0xffffffffu, sw, 2);
            rowsum += xs[m * 2 + h] + sw / se;   // identical in all 4 tig lanes
        }
    }
    #pragma unroll
    for (int m = 16; m; m >>= 1) rowsum += __shfl_xor_sync(0xffffffffu, rowsum, m);
    if (lane == 0) swp[warp] = rowsum * 0.25f;
    __syncthreads();
    if (tid == 0) {
        float s = 0.f;
        #pragma unroll
        for (int i = 0; i < NWARP; i++) s += swp[i];
        atomicAdd(&g_acc, (double)s);
    }
}

// ---------------- kernel 4: finalize scalar ----------------
__global__ void finalize_kernel(float* __restrict__ out, int N) {
    out[0] = (float)(0.1 * g_acc / (double)N);
}

// ---------------- launch ----------------
extern "C" void kernel_launch(void* const* d_in, const int* in_sizes, int n_in,
                              void* d_out, int out_size) {
    const float* x    = (const float*)d_in[0];
    const float* cent = (const float*)d_in[1];
    const void*  ap   = d_in[2];
    int N = in_sizes[0] / D_EMBED;

    cudaFuncSetAttribute(main_kernel, cudaFuncAttributeMaxDynamicSharedMemorySize, SMEM_BYTES);

    prep_kernel<<<2, 1024>>>(cent);
    fill_kernel<<<32, 256>>>(cent);
    main_kernel<<<N / ROWS_CTA, 512, SMEM_BYTES>>>(x, ap);
    finalize_kernel<<<1, 1>>>((float*)d_out, N);
}